// round 1
// baseline (speedup 1.0000x reference)
#include <cuda_runtime.h>

#define NQ 4
#define NH 8
#define NL 2
#define CROW 16            // padded floats per t012 row: [i0:(a,az,ax,pad)]*4
#define CPH (27 * CROW)    // 432 floats per head
#define TOK_PER_BLK 128
#define NTHREADS 128

// Pauli coefficient table: per head, per t012 (27), per ev-component i (4):
// (m_I, m_Z3, m_X3, 0) so that ev_i = sum_t012 u3[t012] * (a0 + a1*cos3 + a2*sin3)
__device__ float g_coef[NH * CPH];

// ---------------------------------------------------------------------------
// Kernel A: per-head precompute. Build U_h (fixed part of the circuit applied
// to the 16 basis states), then Pauli-expand M_i = U^dag Z_i U over {I,Z,X}^4.
// ---------------------------------------------------------------------------
__global__ void qmh_precompute_kernel(const float* __restrict__ params) {
    __shared__ float Ur[16][16];
    __shared__ float Ui[16][16];
    const int h = blockIdx.x;
    const int tid = threadIdx.x;

    if (tid < 16) {
        #pragma unroll
        for (int b = 0; b < 16; b++) {
            Ur[b][tid] = (b == tid) ? 1.0f : 0.0f;
            Ui[b][tid] = 0.0f;
        }
    }
    __syncthreads();

    if (tid < 16) {
        const int j = tid;  // column = input basis state
        const float* p = params + h * NL * NQ * 3;
        for (int l = 0; l < NL; l++) {
            for (int q = 0; q < NQ; q++) {
                const int m = 1 << (3 - q);
                const float tx = p[(l * NQ + q) * 3 + 0];
                const float ty = p[(l * NQ + q) * 3 + 1];
                const float tz = p[(l * NQ + q) * 3 + 2];
                float c, s;
                // RX(t): [[c, -is], [-is, c]]
                c = cosf(0.5f * tx); s = sinf(0.5f * tx);
                for (int b0 = 0; b0 < 16; b0++) if (!(b0 & m)) {
                    const int b1 = b0 | m;
                    float ar = Ur[b0][j], ai = Ui[b0][j];
                    float br = Ur[b1][j], bi = Ui[b1][j];
                    Ur[b0][j] = c * ar + s * bi;  Ui[b0][j] = c * ai - s * br;
                    Ur[b1][j] = c * br + s * ai;  Ui[b1][j] = c * bi - s * ar;
                }
                // RY(t): [[c, -s], [s, c]]
                c = cosf(0.5f * ty); s = sinf(0.5f * ty);
                for (int b0 = 0; b0 < 16; b0++) if (!(b0 & m)) {
                    const int b1 = b0 | m;
                    float ar = Ur[b0][j], ai = Ui[b0][j];
                    float br = Ur[b1][j], bi = Ui[b1][j];
                    Ur[b0][j] = c * ar - s * br;  Ui[b0][j] = c * ai - s * bi;
                    Ur[b1][j] = s * ar + c * br;  Ui[b1][j] = s * ai + c * bi;
                }
                // RZ(t): diag(e^{-it/2}, e^{it/2})
                c = cosf(0.5f * tz); s = sinf(0.5f * tz);
                for (int b0 = 0; b0 < 16; b0++) if (!(b0 & m)) {
                    const int b1 = b0 | m;
                    float ar = Ur[b0][j], ai = Ui[b0][j];
                    float br = Ur[b1][j], bi = Ui[b1][j];
                    Ur[b0][j] = c * ar + s * ai;  Ui[b0][j] = c * ai - s * ar;
                    Ur[b1][j] = c * br - s * bi;  Ui[b1][j] = c * bi + s * br;
                }
            }
            // CNOT chain (0,1),(1,2),(2,3),(3,0) : if bit c set, flip bit t
            const int cq[4] = {0, 1, 2, 3};
            const int tq[4] = {1, 2, 3, 0};
            for (int g = 0; g < 4; g++) {
                const int mc = 1 << (3 - cq[g]);
                const int mt = 1 << (3 - tq[g]);
                for (int b = 0; b < 16; b++) {
                    if ((b & mc) && !(b & mt)) {
                        const int b2 = b | mt;
                        float t0 = Ur[b][j]; Ur[b][j] = Ur[b2][j]; Ur[b2][j] = t0;
                        float t1 = Ui[b][j]; Ui[b][j] = Ui[b2][j]; Ui[b2][j] = t1;
                    }
                }
            }
        }
    }
    __syncthreads();

    // Pauli coefficients: m_{i,P} = (1/16) Tr(M_i P),
    // M_i[j,k] = sum_b z_i(b) conj(U[b,j]) U[b,k];  P in {I,Z,X}^4 is a signed
    // permutation: P[k,j] != 0 only at k = j ^ xmask, value = (-1)^{popc(j&zmask)}.
    for (int s = tid; s < CPH; s += blockDim.x) {
        const int t012 = s >> 4;
        const int r = s & 15;
        const int i = r >> 2;
        const int t3 = r & 3;
        float outv = 0.0f;
        if (t3 < 3) {
            int d0 = t012 / 9, d1 = (t012 / 3) % 3, d2 = t012 % 3, d3 = t3;
            int dig[4] = {d0, d1, d2, d3};
            int xmask = 0, zmask = 0;
            #pragma unroll
            for (int q = 0; q < 4; q++) {
                if (dig[q] == 2) xmask |= 1 << (3 - q);
                if (dig[q] == 1) zmask |= 1 << (3 - q);
            }
            const int zbit = 1 << (3 - i);
            float sum = 0.0f;
            for (int j = 0; j < 16; j++) {
                const int k = j ^ xmask;
                const float ph = (__popc(j & zmask) & 1) ? -1.0f : 1.0f;
                float mjk = 0.0f;
                #pragma unroll
                for (int b = 0; b < 16; b++) {
                    const float z = (b & zbit) ? -1.0f : 1.0f;
                    mjk += z * (Ur[b][j] * Ur[b][k] + Ui[b][j] * Ui[b][k]);
                }
                sum += ph * mjk;
            }
            outv = sum * (1.0f / 16.0f);
        }
        g_coef[h * CPH + s] = outv;
    }
}

// ---------------------------------------------------------------------------
// Kernel B: per-token evaluation. One thread = one token.
// ---------------------------------------------------------------------------
__global__ __launch_bounds__(NTHREADS, 4)
void qmh_main_kernel(const float* __restrict__ x,
                     const float* __restrict__ Wout,
                     const float* __restrict__ bout,
                     float* __restrict__ out) {
    __shared__ float sCoef[NH * CPH];        // 13824 B
    __shared__ float sW[32 * 32];            // 4096 B
    __shared__ float sB[32];
    __shared__ float sTile[TOK_PER_BLK][33]; // 16896 B, padded vs bank conflicts

    const int tid = threadIdx.x;
    const long base = (long)blockIdx.x * TOK_PER_BLK * 32;

    for (int i = tid; i < NH * CPH; i += NTHREADS) sCoef[i] = g_coef[i];
    for (int i = tid; i < 1024; i += NTHREADS) sW[i] = Wout[i];
    if (tid < 32) sB[tid] = bout[tid];
    for (int i = tid; i < TOK_PER_BLK * 32; i += NTHREADS)
        sTile[i >> 5][i & 31] = x[base + i];
    __syncthreads();

    float acc[32];
    #pragma unroll
    for (int e = 0; e < 32; e++) acc[e] = sB[e];

    #pragma unroll 1
    for (int h = 0; h < NH; h++) {
        float c0, s0, c1, s1, c2, s2, c3, s3;
        __sincosf(sTile[tid][4 * h + 0], &s0, &c0);
        __sincosf(sTile[tid][4 * h + 1], &s1, &c1);
        __sincosf(sTile[tid][4 * h + 2], &s2, &c2);
        __sincosf(sTile[tid][4 * h + 3], &s3, &c3);

        float u2[9];
        u2[0] = 1.0f;  u2[1] = c1;       u2[2] = s1;
        u2[3] = c0;    u2[4] = c0 * c1;  u2[5] = c0 * s1;
        u2[6] = s0;    u2[7] = s0 * c1;  u2[8] = s0 * s1;
        float u3[27];
        #pragma unroll
        for (int k = 0; k < 9; k++) {
            u3[3 * k + 0] = u2[k];
            u3[3 * k + 1] = u2[k] * c2;
            u3[3 * k + 2] = u2[k] * s2;
        }

        float e0 = 0.0f, e1 = 0.0f, e2 = 0.0f, e3 = 0.0f;
        const float4* C = (const float4*)&sCoef[h * CPH];
        #pragma unroll
        for (int t = 0; t < 27; t++) {
            const float u = u3[t];
            float4 q0 = C[t * 4 + 0];
            float4 q1 = C[t * 4 + 1];
            float4 q2 = C[t * 4 + 2];
            float4 q3 = C[t * 4 + 3];
            e0 += u * (q0.x + q0.y * c3 + q0.z * s3);
            e1 += u * (q1.x + q1.y * c3 + q1.z * s3);
            e2 += u * (q2.x + q2.y * c3 + q2.z * s3);
            e3 += u * (q3.x + q3.y * c3 + q3.z * s3);
        }

        // Fold W_out columns for this head into the 32 output accumulators.
        const float4* Wr = (const float4*)&sW[0];
        #pragma unroll
        for (int e = 0; e < 32; e++) {
            float4 w4 = Wr[e * 8 + h];  // sW[e*32 + 4h .. +3]
            acc[e] += w4.x * e0 + w4.y * e1 + w4.z * e2 + w4.w * e3;
        }
    }

    #pragma unroll
    for (int e = 0; e < 32; e++) sTile[tid][e] = acc[e];
    __syncthreads();
    for (int i = tid; i < TOK_PER_BLK * 32; i += NTHREADS)
        out[base + i] = sTile[i >> 5][i & 31];
}

extern "C" void kernel_launch(void* const* d_in, const int* in_sizes, int n_in,
                              void* d_out, int out_size) {
    const float* x      = (const float*)d_in[0];  // (32, 4096, 32)
    const float* params = (const float*)d_in[1];  // (8, 2, 4, 3)
    const float* W_out  = (const float*)d_in[2];  // (32, 32)
    const float* b_out  = (const float*)d_in[3];  // (32,)
    float* out = (float*)d_out;

    const int tokens = in_sizes[0] / 32;          // B*S = 131072
    const int nblocks = (tokens + TOK_PER_BLK - 1) / TOK_PER_BLK;

    qmh_precompute_kernel<<<NH, 128>>>(params);
    qmh_main_kernel<<<nblocks, NTHREADS>>>(x, W_out, b_out, out);
}

// round 5
// speedup vs baseline: 1.2357x; 1.2357x over previous
#include <cuda_runtime.h>

#define NH 8
#define NT 27
#define CPH_DUP (NT * 12 * 2)          // 648 floats per head (duplicated)
#define COEF_FLOATS (NH * CPH_DUP)     // 5184 floats

__device__ float g_coef[COEF_FLOATS];

typedef unsigned long long u64;

__device__ __forceinline__ u64 pk(float lo, float hi) {
    u64 r; asm("mov.b64 %0, {%1, %2};" : "=l"(r) : "f"(lo), "f"(hi)); return r;
}
__device__ __forceinline__ u64 fma2(u64 a, u64 b, u64 c) {
    u64 r; asm("fma.rn.f32x2 %0, %1, %2, %3;" : "=l"(r) : "l"(a), "l"(b), "l"(c)); return r;
}
__device__ __forceinline__ u64 mul2(u64 a, u64 b) {
    u64 r; asm("mul.rn.f32x2 %0, %1, %2;" : "=l"(r) : "l"(a), "l"(b)); return r;
}

// ---------------------------------------------------------------------------
// Kernel A: per-head precompute. Column unitary built fully in REGISTERS
// (16 complex amplitudes per thread, all gate loops unrolled), then Pauli
// expansion m[h][t012][i][sel] written DUPLICATED for packed f32x2 loads.
// ---------------------------------------------------------------------------
__global__ void qmh_precompute_kernel(const float* __restrict__ params) {
    __shared__ float Ur[16][17];
    __shared__ float Ui[16][17];
    const int h = blockIdx.x;
    const int tid = threadIdx.x;

    if (tid < 16) {
        float ur[16], ui[16];
        #pragma unroll
        for (int b = 0; b < 16; b++) { ur[b] = (b == tid) ? 1.0f : 0.0f; ui[b] = 0.0f; }
        const float* p = params + h * 24;
        #pragma unroll
        for (int l = 0; l < 2; l++) {
            #pragma unroll
            for (int q = 0; q < 4; q++) {
                const int m = 1 << (3 - q);
                const float tx = p[(l * 4 + q) * 3 + 0];
                const float ty = p[(l * 4 + q) * 3 + 1];
                const float tz = p[(l * 4 + q) * 3 + 2];
                float c, s;
                c = cosf(0.5f * tx); s = sinf(0.5f * tx);     // RX
                #pragma unroll
                for (int b0 = 0; b0 < 16; b0++) if (!(b0 & m)) {
                    const int b1 = b0 | m;
                    float ar = ur[b0], ai = ui[b0], br = ur[b1], bi = ui[b1];
                    ur[b0] = c * ar + s * bi;  ui[b0] = c * ai - s * br;
                    ur[b1] = c * br + s * ai;  ui[b1] = c * bi - s * ar;
                }
                c = cosf(0.5f * ty); s = sinf(0.5f * ty);     // RY
                #pragma unroll
                for (int b0 = 0; b0 < 16; b0++) if (!(b0 & m)) {
                    const int b1 = b0 | m;
                    float ar = ur[b0], ai = ui[b0], br = ur[b1], bi = ui[b1];
                    ur[b0] = c * ar - s * br;  ui[b0] = c * ai - s * bi;
                    ur[b1] = s * ar + c * br;  ui[b1] = s * ai + c * bi;
                }
                c = cosf(0.5f * tz); s = sinf(0.5f * tz);     // RZ
                #pragma unroll
                for (int b0 = 0; b0 < 16; b0++) if (!(b0 & m)) {
                    const int b1 = b0 | m;
                    float ar = ur[b0], ai = ui[b0], br = ur[b1], bi = ui[b1];
                    ur[b0] = c * ar + s * ai;  ui[b0] = c * ai - s * ar;
                    ur[b1] = c * br - s * bi;  ui[b1] = c * bi + s * br;
                }
            }
            #pragma unroll
            for (int g = 0; g < 4; g++) {                      // CNOT chain
                const int mc = 1 << (3 - g);
                const int mt = 1 << (3 - ((g + 1) & 3));
                #pragma unroll
                for (int b = 0; b < 16; b++) if ((b & mc) && !(b & mt)) {
                    const int b2 = b | mt;
                    float t0 = ur[b]; ur[b] = ur[b2]; ur[b2] = t0;
                    float t1 = ui[b]; ui[b] = ui[b2]; ui[b2] = t1;
                }
            }
        }
        #pragma unroll
        for (int b = 0; b < 16; b++) { Ur[b][tid] = ur[b]; Ui[b][tid] = ui[b]; }
    }
    __syncthreads();

    // m[h][t][i][sel] = (1/16) Tr(M_i P);  P indexed by digits (d0,d1,d2,sel),
    // digit: 0=I, 1=Z, 2=X.
    for (int s = tid; s < NT * 12; s += blockDim.x) {
        const int t = s / 12;
        const int rem = s % 12;
        const int i = rem / 3;
        const int sel = rem % 3;
        const int d0 = t / 9, d1 = (t / 3) % 3, d2 = t % 3, d3 = sel;
        int dig[4] = {d0, d1, d2, d3};
        int xmask = 0, zmask = 0;
        #pragma unroll
        for (int q = 0; q < 4; q++) {
            if (dig[q] == 2) xmask |= 1 << (3 - q);
            if (dig[q] == 1) zmask |= 1 << (3 - q);
        }
        const int zbit = 1 << (3 - i);
        float sum = 0.0f;
        for (int j = 0; j < 16; j++) {
            const int k = j ^ xmask;
            const float ph = (__popc(j & zmask) & 1) ? -1.0f : 1.0f;
            float mjk = 0.0f;
            #pragma unroll
            for (int b = 0; b < 16; b++) {
                const float z = (b & zbit) ? -1.0f : 1.0f;
                mjk += z * (Ur[b][j] * Ur[b][k] + Ui[b][j] * Ui[b][k]);
            }
            sum += ph * mjk;
        }
        const float v = sum * (1.0f / 16.0f);
        const int o = ((h * NT + t) * 12 + i * 3 + sel) * 2;
        g_coef[o] = v;
        g_coef[o + 1] = v;
    }
}

// ---------------------------------------------------------------------------
// Kernel B: 4 tokens/thread as 2 packed f32x2 pairs. Phase 1: ev via packed
// Pauli contraction (coef broadcast-loaded pre-duplicated). Phase 2: warp-
// cooperative GEMV, lane = output column, W row in registers.
// ---------------------------------------------------------------------------
#define TPB 128
#define TOKS_PER_BLK 512
#define EVROW 34                       // u64 per pair row (padded)
#define EV_OFF_F 5184                  // float offset of sEvP
#define W_OFF_F (EV_OFF_F + 256 * EVROW * 2)
#define SMEM_FLOATS (W_OFF_F + 1024)
#define SMEM_BYTES (SMEM_FLOATS * 4)

__global__ __launch_bounds__(TPB, 2)
void qmh_main_kernel(const float* __restrict__ x,
                     const float* __restrict__ Wout,
                     const float* __restrict__ bout,
                     float* __restrict__ out) {
    extern __shared__ float dsm[];
    float* sCoef = dsm;
    u64*   sEvP  = (u64*)(dsm + EV_OFF_F);
    float* sW    = dsm + W_OFF_F;

    const int tid = threadIdx.x;
    const long base = (long)blockIdx.x * TOKS_PER_BLK;

    for (int i = tid; i < COEF_FLOATS; i += TPB) sCoef[i] = g_coef[i];
    for (int i = tid; i < 1024; i += TPB) sW[i] = Wout[i];
    __syncthreads();

    // ---------------- Phase 1: packed ev computation -----------------------
    const float* xb = x + base * 32;
    const u64 ONE2 = 0x3F8000003F800000ULL;   // (1.0f, 1.0f)

    #pragma unroll 1
    for (int h = 0; h < NH; h++) {
        float av[4][4];
        #pragma unroll
        for (int tk = 0; tk < 4; tk++) {
            float4 a4 = *(const float4*)(xb + ((long)tk * 128 + tid) * 32 + 4 * h);
            av[tk][0] = a4.x; av[tk][1] = a4.y; av[tk][2] = a4.z; av[tk][3] = a4.w;
        }
        float cc[4][4], ss[4][4];
        #pragma unroll
        for (int tk = 0; tk < 4; tk++)
            #pragma unroll
            for (int q = 0; q < 4; q++)
                __sincosf(av[tk][q], &ss[tk][q], &cc[tk][q]);

        u64 u2[2][9], C2[2], S2[2], C3[2], S3[2];
        #pragma unroll
        for (int P = 0; P < 2; P++) {
            const int lo = 2 * P, hi = 2 * P + 1;
            u64 C0 = pk(cc[lo][0], cc[hi][0]);
            u64 S0 = pk(ss[lo][0], ss[hi][0]);
            u64 C1 = pk(cc[lo][1], cc[hi][1]);
            u64 S1 = pk(ss[lo][1], ss[hi][1]);
            C2[P] = pk(cc[lo][2], cc[hi][2]);
            S2[P] = pk(ss[lo][2], ss[hi][2]);
            C3[P] = pk(cc[lo][3], cc[hi][3]);
            S3[P] = pk(ss[lo][3], ss[hi][3]);
            u2[P][0] = ONE2;          u2[P][1] = C1;            u2[P][2] = S1;
            u2[P][3] = C0;            u2[P][4] = mul2(C0, C1);  u2[P][5] = mul2(C0, S1);
            u2[P][6] = S0;            u2[P][7] = mul2(S0, C1);  u2[P][8] = mul2(S0, S1);
        }

        u64 e[2][4];
        #pragma unroll
        for (int P = 0; P < 2; P++)
            #pragma unroll
            for (int i = 0; i < 4; i++) e[P][i] = 0ULL;

        const ulonglong2* Cp = (const ulonglong2*)(sCoef + h * CPH_DUP);
        #pragma unroll
        for (int t = 0; t < NT; t++) {
            const int k = t / 3, r = t % 3;
            ulonglong2 v0 = Cp[t * 6 + 0];   // a0 | az0
            ulonglong2 v1 = Cp[t * 6 + 1];   // ax0 | a1
            ulonglong2 v2 = Cp[t * 6 + 2];   // az1 | ax1
            ulonglong2 v3 = Cp[t * 6 + 3];   // a2 | az2
            ulonglong2 v4 = Cp[t * 6 + 4];   // ax2 | a3
            ulonglong2 v5 = Cp[t * 6 + 5];   // az3 | ax3
            #pragma unroll
            for (int P = 0; P < 2; P++) {
                u64 u = (r == 0) ? u2[P][k]
                      : mul2(u2[P][k], (r == 1) ? C2[P] : S2[P]);
                u64 tmp;
                tmp = fma2(v0.y, C3[P], v0.x);
                tmp = fma2(v1.x, S3[P], tmp);
                e[P][0] = fma2(u, tmp, e[P][0]);
                tmp = fma2(v2.x, C3[P], v1.y);
                tmp = fma2(v2.y, S3[P], tmp);
                e[P][1] = fma2(u, tmp, e[P][1]);
                tmp = fma2(v3.y, C3[P], v3.x);
                tmp = fma2(v4.x, S3[P], tmp);
                e[P][2] = fma2(u, tmp, e[P][2]);
                tmp = fma2(v5.x, C3[P], v4.y);
                tmp = fma2(v5.y, S3[P], tmp);
                e[P][3] = fma2(u, tmp, e[P][3]);
            }
        }

        #pragma unroll
        for (int P = 0; P < 2; P++) {
            u64* row = sEvP + (size_t)(tid + 128 * P) * EVROW + h * 4;
            ulonglong2 w01; w01.x = e[P][0]; w01.y = e[P][1];
            ulonglong2 w23; w23.x = e[P][2]; w23.y = e[P][3];
            *(ulonglong2*)(row)     = w01;
            *(ulonglong2*)(row + 2) = w23;
        }
    }
    __syncthreads();

    // ---------------- Phase 2: warp-cooperative GEMV -----------------------
    const int lane = tid & 31;
    const int wp = tid >> 5;
    float wrow[32];
    #pragma unroll
    for (int j4 = 0; j4 < 8; j4++) {
        float4 t4 = *(const float4*)(sW + lane * 32 + j4 * 4);
        wrow[j4 * 4 + 0] = t4.x; wrow[j4 * 4 + 1] = t4.y;
        wrow[j4 * 4 + 2] = t4.z; wrow[j4 * 4 + 3] = t4.w;
    }
    const float bias = bout[lane];

    #pragma unroll 2
    for (int pi = 0; pi < 64; pi++) {
        const int p = wp * 64 + pi;
        const float* rf = (const float*)(sEvP + (size_t)p * EVROW);
        float accLo = bias, accHi = bias;
        #pragma unroll
        for (int m = 0; m < 16; m++) {
            // float4 = (lo_{2m}, hi_{2m}, lo_{2m+1}, hi_{2m+1})
            float4 q = ((const float4*)rf)[m];
            accLo = fmaf(wrow[2 * m],     q.x, accLo);
            accHi = fmaf(wrow[2 * m],     q.y, accHi);
            accLo = fmaf(wrow[2 * m + 1], q.z, accLo);
            accHi = fmaf(wrow[2 * m + 1], q.w, accHi);
        }
        const long tok0 = base + p + (p < 128 ? 0 : 128);
        out[tok0 * 32 + lane]         = accLo;
        out[(tok0 + 128) * 32 + lane] = accHi;
    }
}

extern "C" void kernel_launch(void* const* d_in, const int* in_sizes, int n_in,
                              void* d_out, int out_size) {
    const float* x      = (const float*)d_in[0];  // (32, 4096, 32)
    const float* params = (const float*)d_in[1];  // (8, 2, 4, 3)
    const float* W_out  = (const float*)d_in[2];  // (32, 32)
    const float* b_out  = (const float*)d_in[3];  // (32,)
    float* out = (float*)d_out;

    const int tokens = in_sizes[0] / 32;          // 131072
    const int nblocks = tokens / TOKS_PER_BLK;    // 256

    cudaFuncSetAttribute(qmh_main_kernel,
                         cudaFuncAttributeMaxDynamicSharedMemorySize, SMEM_BYTES);

    qmh_precompute_kernel<<<NH, 256>>>(params);
    qmh_main_kernel<<<nblocks, TPB, SMEM_BYTES>>>(x, W_out, b_out, out);
}